// round 14
// baseline (speedup 1.0000x reference)
#include <cuda_runtime.h>
#include <cstdint>

// HebbianNet closed form per layer:
//   z[b,o] = sum_i v[b,i]*W[o,i];  vj = relu(z + bias[o])
//   out    = vj + r*( A*S2[b] + Bc*z + (C*vj + D)*S1[b] )
// A,Bc,C,D folded from cw1/cb1/cw2/cb2; r = RATE/batch_num.
// Shapes: B=8, K=1024 all layers, O = 1024,1024,512.
//
// R13 structure (no V smem staging) with the PDL-legal load path:
// V is read via asm-volatile ld.global.cg (coherent L2; cannot be hoisted
// across griddepcontrol.wait by nvcc or ptxas — unlike __ldg/ld.global.nc,
// whose "invariant for kernel lifetime" contract R13 violated).
// W staged to smem via cp.async BEFORE the wait (independent of
// predecessor). PDL launches for layers 2,3.

#define B_DIM   8
#define K_DIM   1024
#define RATE_F  0.001f
#define NTHR    256
#define VSTRIDE 257          // float4 row stride (conflict-free padding)

__device__ __align__(16) float g_act1[B_DIM * K_DIM];
__device__ __align__(16) float g_act2[B_DIM * K_DIM];

__device__ __forceinline__ void cp_async16(const float4* smem_dst, const float4* gsrc)
{
    uint32_t sa = (uint32_t)__cvta_generic_to_shared(smem_dst);
    asm volatile("cp.async.cg.shared.global [%0], [%1], 16;" :: "r"(sa), "l"(gsrc));
}
__device__ __forceinline__ void cp_commit() { asm volatile("cp.async.commit_group;"); }
__device__ __forceinline__ void cp_wait0()  { asm volatile("cp.async.wait_group 0;"); }

__device__ __forceinline__ void fma2(unsigned long long& acc,
                                     unsigned long long a, unsigned long long b)
{
    asm("fma.rn.f32x2 %0, %1, %2, %3;" : "=l"(acc) : "l"(a), "l"(b), "l"(acc));
}

// coherent (L2) 16B loads that can NOT be hoisted across griddepcontrol.wait
__device__ __forceinline__ float4 ldcg_f4(const float4* p)
{
    float4 v;
    asm volatile("ld.global.cg.v4.f32 {%0,%1,%2,%3}, [%4];"
                 : "=f"(v.x), "=f"(v.y), "=f"(v.z), "=f"(v.w) : "l"(p));
    return v;
}
__device__ __forceinline__ ulonglong2 ldcg_u64x2(const ulonglong2* p)
{
    ulonglong2 v;
    asm volatile("ld.global.cg.v2.u64 {%0,%1}, [%2];"
                 : "=l"(v.x), "=l"(v.y) : "l"(p));
    return v;
}

template<int ROWS, bool PDL_WAIT>   // ROWS: 8 (layers 1-2), 4 (layer 3)
__global__ __launch_bounds__(NTHR, 1)
void hebbian_layer(const float* __restrict__ V,      // (8,1024)
                   const float* __restrict__ W,      // (O,1024)
                   const float* __restrict__ bias,   // (O,)
                   const float* __restrict__ cw1, const float* __restrict__ cb1,
                   const float* __restrict__ cw2, const float* __restrict__ cb2,
                   const int*   __restrict__ bn,
                   float*       __restrict__ out,    // (8,O)
                   int O)
{
    constexpr int SLOTS = ROWS * 8;        // lanes with a (row,batch) identity
    constexpr int NQ    = 256 / SLOTS;     // K-chunks: ROWS=8 -> 4, ROWS=4 -> 8
    constexpr int CHUNK = 256 / NQ;        // 16B units per chunk: 64 or 32
    static_assert(NQ * SLOTS == 256, "red sized 256 floats");
    static_assert(NQ * CHUNK == 256, "full K coverage");

    extern __shared__ float4 sm[];
    float4* Ws  = sm;                         // ROWS * 257 float4
    float*  red = (float*)(Ws + ROWS * VSTRIDE);  // 256 floats
    float*  S1s = red + 256;
    float*  S2s = S1s + 8;

    const int tid  = threadIdx.x;
    const int wid  = tid >> 5;
    const int lane = tid & 31;
    const int o_base = blockIdx.x * ROWS;

    // let dependent kernels launch immediately (their W staging overlaps us)
    asm volatile("griddepcontrol.launch_dependents;");

    // ---- stage W slice to smem (independent of predecessor) ----------------
    const float4* Wg = (const float4*)(W + (size_t)o_base * K_DIM);
#pragma unroll
    for (int m = 0; m < ROWS; ++m) {
        int x = tid + m * NTHR;
        cp_async16(&Ws[(x >> 8) * VSTRIDE + (x & 255)], &Wg[x]);
    }
    cp_commit();

    // ---- uniform scalar folding + bias prefetch (also independent) ---------
    float A = 0.f, Bc = 0.f, C = 0.f, D = 0.f;
#pragma unroll
    for (int h = 0; h < 8; ++h) {
        float e = cw2[h];
        A  = fmaf(e, cw1[3*h + 0], A);
        Bc = fmaf(e, cw1[3*h + 1], Bc);
        C  = fmaf(e, cw1[3*h + 2], C);
        D  = fmaf(e, cb1[h],       D);
    }
    D += cb2[0];
    const float rr = RATE_F / (float)bn[0];

    float bias_r = 0.f;
    if (tid < SLOTS) bias_r = bias[o_base + (tid >> 3)];

    // ---- wait for predecessor grid (activations valid), W smem ready -------
    if (PDL_WAIT)
        asm volatile("griddepcontrol.wait;" ::: "memory");
    cp_wait0();
    __syncthreads();        // all warps' W staging visible

    // ---- per-batch stats: warp w (0..7) -> batch w, V from global (.cg) ----
    {
        const float4* Vg = (const float4*)V + wid * 256;
        float s1 = 0.f, s2 = 0.f;
#pragma unroll
        for (int m = 0; m < 8; ++m) {
            float4 v = ldcg_f4(&Vg[m * 32 + lane]);
            s1 += v.x + v.y + v.z + v.w;
            s2 = fmaf(v.x, v.x, s2); s2 = fmaf(v.y, v.y, s2);
            s2 = fmaf(v.z, v.z, s2); s2 = fmaf(v.w, v.w, s2);
        }
#pragma unroll
        for (int off = 16; off > 0; off >>= 1) {
            s1 += __shfl_xor_sync(0xffffffffu, s1, off);
            s2 += __shfl_xor_sync(0xffffffffu, s2, off);
        }
        if (lane == 0) { S1s[wid] = s1; S2s[wid] = s2; }
    }

    // ---- GEMV: V from global (.cg, 4x lane dedup), W from smem -------------
    int q, s, row;
    if (ROWS == 8) {
        q   = wid >> 1;                 // 0..3   (NQ=4)
        int g = wid & 1;                // row group
        s   = g * 32 + lane;            // 0..63  (SLOTS=64)
        row = g * 4 + (lane >> 3);
    } else {
        q   = wid;                      // 0..7   (NQ=8)
        s   = lane;                     // 0..31  (SLOTS=32)
        row = lane >> 3;
    }
    const int b = lane & 7;

    const ulonglong2* vp = (const ulonglong2*)V + b * 256 + q * CHUNK;
    const ulonglong2* wp = (const ulonglong2*)(Ws + row * VSTRIDE + q * CHUNK);

    unsigned long long A0 = 0ull, A1 = 0ull, A2 = 0ull, A3 = 0ull;
#pragma unroll
    for (int i = 0; i < CHUNK; i += 2) {
        ulonglong2 v0 = ldcg_u64x2(&vp[i]);
        ulonglong2 v1 = ldcg_u64x2(&vp[i+1]);
        ulonglong2 w0 = wp[i];
        ulonglong2 w1 = wp[i+1];
        fma2(A0, w0.x, v0.x);  fma2(A1, w0.y, v0.y);
        fma2(A2, w1.x, v1.x);  fma2(A3, w1.y, v1.y);
    }
    float2 f0 = *(float2*)&A0, f1 = *(float2*)&A1;
    float2 f2 = *(float2*)&A2, f3 = *(float2*)&A3;
    red[q * SLOTS + s] = ((f0.x + f0.y) + (f1.x + f1.y))
                       + ((f2.x + f2.y) + (f3.x + f3.y));
    __syncthreads();

    // ---- combine K-chunks + epilogue ----------------------------------------
    if (tid < SLOTS) {
        const int r  = tid >> 3;
        const int bb = tid & 7;
        const int o  = o_base + r;

        float z = 0.f;
#pragma unroll
        for (int qq = 0; qq < NQ; ++qq) z += red[qq * SLOTS + tid];

        float vj = fmaxf(z + bias_r, 0.f);
        float sh = fmaf(A, S2s[bb], fmaf(Bc, z, (C * vj + D) * S1s[bb]));
        out[(size_t)bb * O + o] = fmaf(rr, sh, vj);
    }
}

extern "C" void kernel_launch(void* const* d_in, const int* in_sizes, int n_in,
                              void* d_out, int out_size)
{
    (void)in_sizes; (void)n_in; (void)out_size;
    const float* x   = (const float*)d_in[0];
    const float* W1  = (const float*)d_in[1];
    const float* b1  = (const float*)d_in[2];
    const float* W2  = (const float*)d_in[3];
    const float* b2  = (const float*)d_in[4];
    const float* W3  = (const float*)d_in[5];
    const float* b3  = (const float*)d_in[6];
    const float* cw1 = (const float*)d_in[7];
    const float* cb1 = (const float*)d_in[8];
    const float* cw2 = (const float*)d_in[9];
    const float* cb2 = (const float*)d_in[10];
    const int*   bn  = (const int*)d_in[11];
    float* outp = (float*)d_out;

    float *act1, *act2;
    cudaGetSymbolAddress((void**)&act1, g_act1);
    cudaGetSymbolAddress((void**)&act2, g_act2);

    const int smem8 = 8 * VSTRIDE * 16 + 256 * 4 + 16 * 4;
    const int smem4 = 4 * VSTRIDE * 16 + 256 * 4 + 16 * 4;
    cudaFuncSetAttribute(hebbian_layer<8, false>,
                         cudaFuncAttributeMaxDynamicSharedMemorySize, smem8);
    cudaFuncSetAttribute(hebbian_layer<8, true>,
                         cudaFuncAttributeMaxDynamicSharedMemorySize, smem8);
    cudaFuncSetAttribute(hebbian_layer<4, true>,
                         cudaFuncAttributeMaxDynamicSharedMemorySize, smem4);

    // layer 1: x -> act1 (plain launch)
    hebbian_layer<8, false><<<128, NTHR, smem8>>>(
        x, W1, b1, cw1, cb1, cw2, cb2, bn, act1, 1024);

    // layers 2,3: PDL launches (prologue overlaps predecessor)
    cudaLaunchAttribute at[1];
    at[0].id = cudaLaunchAttributeProgrammaticStreamSerialization;
    at[0].val.programmaticStreamSerializationAllowed = 1;

    cudaLaunchConfig_t cfg = {};
    cfg.gridDim  = dim3(128, 1, 1);
    cfg.blockDim = dim3(NTHR, 1, 1);
    cfg.stream   = 0;
    cfg.attrs    = at;
    cfg.numAttrs = 1;

    cfg.dynamicSmemBytes = smem8;
    cudaLaunchKernelEx(&cfg, hebbian_layer<8, true>,
                       (const float*)act1, W2, b2, cw1, cb1, cw2, cb2, bn,
                       (float*)act2, 1024);

    cfg.dynamicSmemBytes = smem4;
    cudaLaunchKernelEx(&cfg, hebbian_layer<4, true>,
                       (const float*)act2, W3, b3, cw1, cb1, cw2, cb2, bn,
                       outp, 512);
}

// round 15
// speedup vs baseline: 1.8340x; 1.8340x over previous
#include <cuda_runtime.h>
#include <cstdint>

// HebbianNet closed form per layer:
//   z[b,o] = sum_i v[b,i]*W[o,i];  vj = relu(z + bias[o])
//   out    = vj + r*( A*S2[b] + Bc*z + (C*vj + D)*S1[b] )
// A,Bc,C,D folded from cw1/cb1/cw2/cb2; r = RATE/batch_num.
// Shapes: B=8, K=1024 all layers, O = 1024,1024,512.
//
// FINAL (R11 configuration, best verified: 16.864us, rel_err 6.8e-7):
// 3 kernels; 128 blocks x 256 threads; ROWS=8 (layers 1-2) / 4 (layer 3).
// V+W staged to padded smem via cp.async; packed fma.rn.f32x2 GEMV with
// lane=(row,batch) mapping (no shuffle reduction); PDL overlaps each
// successor's launch + W-staging + scalar-folding with its predecessor,
// with griddepcontrol.wait guarding the activation reads.

#define B_DIM   8
#define K_DIM   1024
#define RATE_F  0.001f
#define NTHR    256
#define VSTRIDE 257          // float4 row stride (conflict-free padding)

__device__ __align__(16) float g_act1[B_DIM * K_DIM];
__device__ __align__(16) float g_act2[B_DIM * K_DIM];

__device__ __forceinline__ void cp_async16(const float4* smem_dst, const float4* gsrc)
{
    uint32_t sa = (uint32_t)__cvta_generic_to_shared(smem_dst);
    asm volatile("cp.async.cg.shared.global [%0], [%1], 16;" :: "r"(sa), "l"(gsrc));
}
__device__ __forceinline__ void cp_commit() { asm volatile("cp.async.commit_group;"); }
__device__ __forceinline__ void cp_wait0()  { asm volatile("cp.async.wait_group 0;"); }

__device__ __forceinline__ void fma2(unsigned long long& acc,
                                     unsigned long long a, unsigned long long b)
{
    asm("fma.rn.f32x2 %0, %1, %2, %3;" : "=l"(acc) : "l"(a), "l"(b), "l"(acc));
}

template<int ROWS, bool PDL_WAIT>   // ROWS: 8 (layers 1-2), 4 (layer 3)
__global__ __launch_bounds__(NTHR, 1)
void hebbian_layer(const float* __restrict__ V,      // (8,1024)
                   const float* __restrict__ W,      // (O,1024)
                   const float* __restrict__ bias,   // (O,)
                   const float* __restrict__ cw1, const float* __restrict__ cb1,
                   const float* __restrict__ cw2, const float* __restrict__ cb2,
                   const int*   __restrict__ bn,
                   float*       __restrict__ out,    // (8,O)
                   int O)
{
    constexpr int SLOTS = ROWS * 8;        // lanes with a (row,batch) identity
    constexpr int NQ    = 256 / SLOTS;     // K-chunks: ROWS=8 -> 4, ROWS=4 -> 8
    constexpr int CHUNK = 256 / NQ;        // float4 per chunk: 64 or 32
    static_assert(NQ * SLOTS == 256, "red sized 256 floats");
    static_assert(NQ * CHUNK == 256, "full K coverage");

    extern __shared__ float4 sm[];
    float4* Vs  = sm;                       // 8 * 257 float4
    float4* Ws  = Vs + 8 * VSTRIDE;         // ROWS * 257 float4
    float*  red = (float*)(Ws + ROWS * VSTRIDE);  // 256 floats
    float*  S1s = red + 256;
    float*  S2s = S1s + 8;

    const int tid  = threadIdx.x;
    const int wid  = tid >> 5;
    const int lane = tid & 31;
    const int o_base = blockIdx.x * ROWS;

    // let dependent kernels launch immediately (their W staging overlaps us)
    asm volatile("griddepcontrol.launch_dependents;");

    // ---- stage W slice (independent of predecessor) -------------------------
    const float4* Wg = (const float4*)(W + (size_t)o_base * K_DIM);
#pragma unroll
    for (int m = 0; m < ROWS; ++m) {
        int x = tid + m * NTHR;
        cp_async16(&Ws[(x >> 8) * VSTRIDE + (x & 255)], &Wg[x]);
    }
    cp_commit();

    // ---- uniform scalar folding + bias prefetch (also independent) ---------
    float A = 0.f, Bc = 0.f, C = 0.f, D = 0.f;
#pragma unroll
    for (int h = 0; h < 8; ++h) {
        float e = cw2[h];
        A  = fmaf(e, cw1[3*h + 0], A);
        Bc = fmaf(e, cw1[3*h + 1], Bc);
        C  = fmaf(e, cw1[3*h + 2], C);
        D  = fmaf(e, cb1[h],       D);
    }
    D += cb2[0];
    const float rr = RATE_F / (float)bn[0];

    float bias_r = 0.f;
    if (tid < SLOTS) bias_r = bias[o_base + (tid >> 3)];

    // ---- wait for predecessor grid completion, then stage V ----------------
    if (PDL_WAIT)
        asm volatile("griddepcontrol.wait;" ::: "memory");

    const float4* Vg = (const float4*)V;
#pragma unroll
    for (int m = 0; m < 8; ++m) {
        int x = tid + m * NTHR;
        cp_async16(&Vs[(x >> 8) * VSTRIDE + (x & 255)], &Vg[x]);
    }
    cp_commit();

    cp_wait0();
    __syncthreads();

    // ---- per-batch stats: warp w (0..7) -> batch w --------------------------
    {
        float s1 = 0.f, s2 = 0.f;
#pragma unroll
        for (int m = 0; m < 8; ++m) {
            float4 v = Vs[wid * VSTRIDE + m * 32 + lane];
            s1 += v.x + v.y + v.z + v.w;
            s2 = fmaf(v.x, v.x, s2); s2 = fmaf(v.y, v.y, s2);
            s2 = fmaf(v.z, v.z, s2); s2 = fmaf(v.w, v.w, s2);
        }
#pragma unroll
        for (int off = 16; off > 0; off >>= 1) {
            s1 += __shfl_xor_sync(0xffffffffu, s1, off);
            s2 += __shfl_xor_sync(0xffffffffu, s2, off);
        }
        if (lane == 0) { S1s[wid] = s1; S2s[wid] = s2; }
    }

    // ---- GEMV: packed f32x2 FMAs, lane owns one (row,batch) ----------------
    int q, s, row;
    if (ROWS == 8) {
        q   = wid >> 1;                 // 0..3   (NQ=4)
        int g = wid & 1;                // row group
        s   = g * 32 + lane;            // 0..63  (SLOTS=64)
        row = g * 4 + (lane >> 3);
    } else {
        q   = wid;                      // 0..7   (NQ=8)
        s   = lane;                     // 0..31  (SLOTS=32)
        row = lane >> 3;
    }
    const int b = lane & 7;

    const ulonglong2* vp = (const ulonglong2*)(Vs + b   * VSTRIDE + q * CHUNK);
    const ulonglong2* wp = (const ulonglong2*)(Ws + row * VSTRIDE + q * CHUNK);

    unsigned long long A0 = 0ull, A1 = 0ull, A2 = 0ull, A3 = 0ull;
#pragma unroll
    for (int i = 0; i < CHUNK; i += 2) {
        ulonglong2 v0 = vp[i],   w0 = wp[i];
        ulonglong2 v1 = vp[i+1], w1 = wp[i+1];
        fma2(A0, w0.x, v0.x);  fma2(A1, w0.y, v0.y);
        fma2(A2, w1.x, v1.x);  fma2(A3, w1.y, v1.y);
    }
    float2 f0 = *(float2*)&A0, f1 = *(float2*)&A1;
    float2 f2 = *(float2*)&A2, f3 = *(float2*)&A3;
    red[q * SLOTS + s] = ((f0.x + f0.y) + (f1.x + f1.y))
                       + ((f2.x + f2.y) + (f3.x + f3.y));
    __syncthreads();

    // ---- combine K-chunks + epilogue ----------------------------------------
    if (tid < SLOTS) {
        const int r  = tid >> 3;
        const int bb = tid & 7;
        const int o  = o_base + r;

        float z = 0.f;
#pragma unroll
        for (int qq = 0; qq < NQ; ++qq) z += red[qq * SLOTS + tid];

        float vj = fmaxf(z + bias_r, 0.f);
        float sh = fmaf(A, S2s[bb], fmaf(Bc, z, (C * vj + D) * S1s[bb]));
        out[(size_t)bb * O + o] = fmaf(rr, sh, vj);
    }
}

extern "C" void kernel_launch(void* const* d_in, const int* in_sizes, int n_in,
                              void* d_out, int out_size)
{
    (void)in_sizes; (void)n_in; (void)out_size;
    const float* x   = (const float*)d_in[0];
    const float* W1  = (const float*)d_in[1];
    const float* b1  = (const float*)d_in[2];
    const float* W2  = (const float*)d_in[3];
    const float* b2  = (const float*)d_in[4];
    const float* W3  = (const float*)d_in[5];
    const float* b3  = (const float*)d_in[6];
    const float* cw1 = (const float*)d_in[7];
    const float* cb1 = (const float*)d_in[8];
    const float* cw2 = (const float*)d_in[9];
    const float* cb2 = (const float*)d_in[10];
    const int*   bn  = (const int*)d_in[11];
    float* outp = (float*)d_out;

    float *act1, *act2;
    cudaGetSymbolAddress((void**)&act1, g_act1);
    cudaGetSymbolAddress((void**)&act2, g_act2);

    const int smem8 = (8 + 8) * VSTRIDE * 16 + 256 * 4 + 16 * 4;
    const int smem4 = (8 + 4) * VSTRIDE * 16 + 256 * 4 + 16 * 4;
    cudaFuncSetAttribute(hebbian_layer<8, false>,
                         cudaFuncAttributeMaxDynamicSharedMemorySize, smem8);
    cudaFuncSetAttribute(hebbian_layer<8, true>,
                         cudaFuncAttributeMaxDynamicSharedMemorySize, smem8);
    cudaFuncSetAttribute(hebbian_layer<4, true>,
                         cudaFuncAttributeMaxDynamicSharedMemorySize, smem4);

    // layer 1: x -> act1 (plain launch)
    hebbian_layer<8, false><<<128, NTHR, smem8>>>(
        x, W1, b1, cw1, cb1, cw2, cb2, bn, act1, 1024);

    // layers 2,3: PDL launches (overlap prologue with predecessor)
    cudaLaunchAttribute at[1];
    at[0].id = cudaLaunchAttributeProgrammaticStreamSerialization;
    at[0].val.programmaticStreamSerializationAllowed = 1;

    cudaLaunchConfig_t cfg = {};
    cfg.gridDim  = dim3(128, 1, 1);
    cfg.blockDim = dim3(NTHR, 1, 1);
    cfg.stream   = 0;            // legacy stream (mapped by capture)
    cfg.attrs    = at;
    cfg.numAttrs = 1;

    cfg.dynamicSmemBytes = smem8;
    cudaLaunchKernelEx(&cfg, hebbian_layer<8, true>,
                       (const float*)act1, W2, b2, cw1, cb1, cw2, cb2, bn,
                       (float*)act2, 1024);

    cfg.dynamicSmemBytes = smem4;
    cudaLaunchKernelEx(&cfg, hebbian_layer<4, true>,
                       (const float*)act2, W3, b3, cw1, cb1, cw2, cb2, bn,
                       outp, 512);
}

// round 16
// speedup vs baseline: 1.8653x; 1.0171x over previous
#include <cuda_runtime.h>
#include <cstdint>

// HebbianNet closed form per layer:
//   z[b,o] = sum_i v[b,i]*W[o,i];  vj = relu(z + bias[o])
//   out    = vj + r*( A*S2[b] + Bc*z + (C*vj + D)*S1[b] )
// A,Bc,C,D folded from cw1/cb1/cw2/cb2; r = RATE/batch_num.
// Shapes: B=8, K=1024 all layers, O = 1024,1024,512.
//
// Best verified config (16.864us) + one local tweak: in layer 1
// (no PDL), V is staged as its own cp.async group BEFORE W, so the
// stats phase starts as soon as V lands while W is still in flight
// (wait_group 1), and only the GEMV waits for W (wait_group 0).
// PDL kernels keep W pre-wait (group 0) / V post-wait (group 1) and
// likewise start stats at wait_group 1.

#define B_DIM   8
#define K_DIM   1024
#define RATE_F  0.001f
#define NTHR    256
#define VSTRIDE 257          // float4 row stride (conflict-free padding)

__device__ __align__(16) float g_act1[B_DIM * K_DIM];
__device__ __align__(16) float g_act2[B_DIM * K_DIM];

__device__ __forceinline__ void cp_async16(const float4* smem_dst, const float4* gsrc)
{
    uint32_t sa = (uint32_t)__cvta_generic_to_shared(smem_dst);
    asm volatile("cp.async.cg.shared.global [%0], [%1], 16;" :: "r"(sa), "l"(gsrc));
}
__device__ __forceinline__ void cp_commit() { asm volatile("cp.async.commit_group;"); }
template<int N> __device__ __forceinline__ void cp_wait()
{ asm volatile("cp.async.wait_group %0;" :: "n"(N)); }

__device__ __forceinline__ void fma2(unsigned long long& acc,
                                     unsigned long long a, unsigned long long b)
{
    asm("fma.rn.f32x2 %0, %1, %2, %3;" : "=l"(acc) : "l"(a), "l"(b), "l"(acc));
}

template<int ROWS, bool PDL_WAIT>   // ROWS: 8 (layers 1-2), 4 (layer 3)
__global__ __launch_bounds__(NTHR, 1)
void hebbian_layer(const float* __restrict__ V,      // (8,1024)
                   const float* __restrict__ W,      // (O,1024)
                   const float* __restrict__ bias,   // (O,)
                   const float* __restrict__ cw1, const float* __restrict__ cb1,
                   const float* __restrict__ cw2, const float* __restrict__ cb2,
                   const int*   __restrict__ bn,
                   float*       __restrict__ out,    // (8,O)
                   int O)
{
    constexpr int SLOTS = ROWS * 8;        // lanes with a (row,batch) identity
    constexpr int NQ    = 256 / SLOTS;     // K-chunks: ROWS=8 -> 4, ROWS=4 -> 8
    constexpr int CHUNK = 256 / NQ;        // float4 per chunk: 64 or 32
    static_assert(NQ * SLOTS == 256, "red sized 256 floats");
    static_assert(NQ * CHUNK == 256, "full K coverage");

    extern __shared__ float4 sm[];
    float4* Vs  = sm;                       // 8 * 257 float4
    float4* Ws  = Vs + 8 * VSTRIDE;         // ROWS * 257 float4
    float*  red = (float*)(Ws + ROWS * VSTRIDE);  // 256 floats
    float*  S1s = red + 256;
    float*  S2s = S1s + 8;

    const int tid  = threadIdx.x;
    const int wid  = tid >> 5;
    const int lane = tid & 31;
    const int o_base = blockIdx.x * ROWS;

    // let dependent kernels launch immediately (their W staging overlaps us)
    asm volatile("griddepcontrol.launch_dependents;");

    const float4* Wg = (const float4*)(W + (size_t)o_base * K_DIM);
    const float4* Vg = (const float4*)V;

    if (!PDL_WAIT) {
        // layer 1: V first (group 0 target of wait<1>), then W
#pragma unroll
        for (int m = 0; m < 8; ++m) {
            int x = tid + m * NTHR;
            cp_async16(&Vs[(x >> 8) * VSTRIDE + (x & 255)], &Vg[x]);
        }
        cp_commit();                          // group: V
#pragma unroll
        for (int m = 0; m < ROWS; ++m) {
            int x = tid + m * NTHR;
            cp_async16(&Ws[(x >> 8) * VSTRIDE + (x & 255)], &Wg[x]);
        }
        cp_commit();                          // group: W
    } else {
        // PDL layers: W must go pre-wait (independent of predecessor)
#pragma unroll
        for (int m = 0; m < ROWS; ++m) {
            int x = tid + m * NTHR;
            cp_async16(&Ws[(x >> 8) * VSTRIDE + (x & 255)], &Wg[x]);
        }
        cp_commit();                          // group: W (lands during predecessor)
    }

    // ---- uniform scalar folding + bias prefetch (overlap load latency) -----
    float A = 0.f, Bc = 0.f, C = 0.f, D = 0.f;
#pragma unroll
    for (int h = 0; h < 8; ++h) {
        float e = cw2[h];
        A  = fmaf(e, cw1[3*h + 0], A);
        Bc = fmaf(e, cw1[3*h + 1], Bc);
        C  = fmaf(e, cw1[3*h + 2], C);
        D  = fmaf(e, cb1[h],       D);
    }
    D += cb2[0];
    const float rr = RATE_F / (float)bn[0];

    float bias_r = 0.f;
    if (tid < SLOTS) bias_r = bias[o_base + (tid >> 3)];

    if (PDL_WAIT) {
        // wait for predecessor grid completion, then stage V (group 2)
        asm volatile("griddepcontrol.wait;" ::: "memory");
#pragma unroll
        for (int m = 0; m < 8; ++m) {
            int x = tid + m * NTHR;
            cp_async16(&Vs[(x >> 8) * VSTRIDE + (x & 255)], &Vg[x]);
        }
        cp_commit();                          // group: V
    }

    // V ready here (wait<1>: at most the newest group pending).
    // layer 1: pending = W; PDL: pending = V... order differs, so:
    //   !PDL: groups [V, W] -> wait<1> = V done. stats OK, W may fly.
    //   PDL:  groups [W, V] -> wait<1> = W done, V pending -> stats
    //         needs V, so PDL path must wait<0> before stats.
    if (!PDL_WAIT) cp_wait<1>();
    else           cp_wait<0>();
    __syncthreads();

    // ---- per-batch stats: warp w (0..7) -> batch w --------------------------
    {
        float s1 = 0.f, s2 = 0.f;
#pragma unroll
        for (int m = 0; m < 8; ++m) {
            float4 v = Vs[wid * VSTRIDE + m * 32 + lane];
            s1 += v.x + v.y + v.z + v.w;
            s2 = fmaf(v.x, v.x, s2); s2 = fmaf(v.y, v.y, s2);
            s2 = fmaf(v.z, v.z, s2); s2 = fmaf(v.w, v.w, s2);
        }
#pragma unroll
        for (int off = 16; off > 0; off >>= 1) {
            s1 += __shfl_xor_sync(0xffffffffu, s1, off);
            s2 += __shfl_xor_sync(0xffffffffu, s2, off);
        }
        if (lane == 0) { S1s[wid] = s1; S2s[wid] = s2; }
    }

    if (!PDL_WAIT) {            // now require W before the GEMV touches it
        cp_wait<0>();
        __syncthreads();
    }

    // ---- GEMV: packed f32x2 FMAs, lane owns one (row,batch) ----------------
    int q, s, row;
    if (ROWS == 8) {
        q   = wid >> 1;                 // 0..3   (NQ=4)
        int g = wid & 1;                // row group
        s   = g * 32 + lane;            // 0..63  (SLOTS=64)
        row = g * 4 + (lane >> 3);
    } else {
        q   = wid;                      // 0..7   (NQ=8)
        s   = lane;                     // 0..31  (SLOTS=32)
        row = lane >> 3;
    }
    const int b = lane & 7;

    const ulonglong2* vp = (const ulonglong2*)(Vs + b   * VSTRIDE + q * CHUNK);
    const ulonglong2* wp = (const ulonglong2*)(Ws + row * VSTRIDE + q * CHUNK);

    unsigned long long A0 = 0ull, A1 = 0ull, A2 = 0ull, A3 = 0ull;
#pragma unroll
    for (int i = 0; i < CHUNK; i += 2) {
        ulonglong2 v0 = vp[i],   w0 = wp[i];
        ulonglong2 v1 = vp[i+1], w1 = wp[i+1];
        fma2(A0, w0.x, v0.x);  fma2(A1, w0.y, v0.y);
        fma2(A2, w1.x, v1.x);  fma2(A3, w1.y, v1.y);
    }
    float2 f0 = *(float2*)&A0, f1 = *(float2*)&A1;
    float2 f2 = *(float2*)&A2, f3 = *(float2*)&A3;
    red[q * SLOTS + s] = ((f0.x + f0.y) + (f1.x + f1.y))
                       + ((f2.x + f2.y) + (f3.x + f3.y));
    __syncthreads();

    // ---- combine K-chunks + epilogue ----------------------------------------
    if (tid < SLOTS) {
        const int r  = tid >> 3;
        const int bb = tid & 7;
        const int o  = o_base + r;

        float z = 0.f;
#pragma unroll
        for (int qq = 0; qq < NQ; ++qq) z += red[qq * SLOTS + tid];

        float vj = fmaxf(z + bias_r, 0.f);
        float sh = fmaf(A, S2s[bb], fmaf(Bc, z, (C * vj + D) * S1s[bb]));
        out[(size_t)bb * O + o] = fmaf(rr, sh, vj);
    }
}

extern "C" void kernel_launch(void* const* d_in, const int* in_sizes, int n_in,
                              void* d_out, int out_size)
{
    (void)in_sizes; (void)n_in; (void)out_size;
    const float* x   = (const float*)d_in[0];
    const float* W1  = (const float*)d_in[1];
    const float* b1  = (const float*)d_in[2];
    const float* W2  = (const float*)d_in[3];
    const float* b2  = (const float*)d_in[4];
    const float* W3  = (const float*)d_in[5];
    const float* b3  = (const float*)d_in[6];
    const float* cw1 = (const float*)d_in[7];
    const float* cb1 = (const float*)d_in[8];
    const float* cw2 = (const float*)d_in[9];
    const float* cb2 = (const float*)d_in[10];
    const int*   bn  = (const int*)d_in[11];
    float* outp = (float*)d_out;

    float *act1, *act2;
    cudaGetSymbolAddress((void**)&act1, g_act1);
    cudaGetSymbolAddress((void**)&act2, g_act2);

    const int smem8 = (8 + 8) * VSTRIDE * 16 + 256 * 4 + 16 * 4;
    const int smem4 = (8 + 4) * VSTRIDE * 16 + 256 * 4 + 16 * 4;
    cudaFuncSetAttribute(hebbian_layer<8, false>,
                         cudaFuncAttributeMaxDynamicSharedMemorySize, smem8);
    cudaFuncSetAttribute(hebbian_layer<8, true>,
                         cudaFuncAttributeMaxDynamicSharedMemorySize, smem8);
    cudaFuncSetAttribute(hebbian_layer<4, true>,
                         cudaFuncAttributeMaxDynamicSharedMemorySize, smem4);

    // layer 1: x -> act1 (plain launch; V-first split-wait staging)
    hebbian_layer<8, false><<<128, NTHR, smem8>>>(
        x, W1, b1, cw1, cb1, cw2, cb2, bn, act1, 1024);

    // layers 2,3: PDL launches (overlap prologue with predecessor)
    cudaLaunchAttribute at[1];
    at[0].id = cudaLaunchAttributeProgrammaticStreamSerialization;
    at[0].val.programmaticStreamSerializationAllowed = 1;

    cudaLaunchConfig_t cfg = {};
    cfg.gridDim  = dim3(128, 1, 1);
    cfg.blockDim = dim3(NTHR, 1, 1);
    cfg.stream   = 0;            // legacy stream (mapped by capture)
    cfg.attrs    = at;
    cfg.numAttrs = 1;

    cfg.dynamicSmemBytes = smem8;
    cudaLaunchKernelEx(&cfg, hebbian_layer<8, true>,
                       (const float*)act1, W2, b2, cw1, cb1, cw2, cb2, bn,
                       (float*)act2, 1024);

    cfg.dynamicSmemBytes = smem4;
    cudaLaunchKernelEx(&cfg, hebbian_layer<4, true>,
                       (const float*)act2, W3, b3, cw1, cb1, cw2, cb2, bn,
                       outp, 512);
}